// round 5
// baseline (speedup 1.0000x reference)
#include <cuda_runtime.h>
#include <cstdint>

#define B_  2
#define L_  2048
#define DM  1024
#define NH  16
#define DQ  64

// Scratch (allocation-free rule: __device__ globals)
__device__ float g_q [(size_t)B_ * NH * L_ * DQ];   // tf32-rounded, pre-scaled by 0.125
__device__ float g_k [(size_t)B_ * NH * L_ * DQ];   // tf32-rounded
__device__ float g_vt[(size_t)B_ * NH * DQ * L_];   // V transposed [b][h][e][l], tf32-rounded
__device__ float g_o [(size_t)B_ * NH * L_ * DQ];   // attn out, tf32-rounded
__device__ float g_y [(size_t)B_ * L_ * DM];
__device__ float g_xr[(size_t)B_ * L_ * DM];        // tf32-rounded x
__device__ float g_wt[(size_t)3 * NH * DQ * DM];    // [z][h][e][d] tf32-rounded
__device__ float g_wot[(size_t)DM * DM];            // [n][k] tf32-rounded
__device__ __align__(16) uint8_t g_mflag[B_ * 16 * 32]; // per (b, qblock128, ktile64) any-mask

__device__ __forceinline__ float to_tf32(float x) {
    asm("cvt.rna.tf32.f32 %0, %0;" : "+f"(x));
    return x;
}

__device__ __forceinline__ void mma8(float c[4], const uint32_t a[4], const uint32_t b[2]) {
    asm volatile(
        "mma.sync.aligned.m16n8k8.row.col.f32.tf32.tf32.f32 "
        "{%0,%1,%2,%3},{%4,%5,%6,%7},{%8,%9},{%0,%1,%2,%3};"
        : "+f"(c[0]), "+f"(c[1]), "+f"(c[2]), "+f"(c[3])
        : "r"(a[0]), "r"(a[1]), "r"(a[2]), "r"(a[3]), "r"(b[0]), "r"(b[1]));
}

__device__ __forceinline__ void cp16(float* s, const float* g) {
    uint32_t sa = (uint32_t)__cvta_generic_to_shared(s);
    asm volatile("cp.async.cg.shared.global [%0], [%1], 16;" :: "r"(sa), "l"(g));
}
__device__ __forceinline__ void cp_commit() { asm volatile("cp.async.commit_group;"); }
template<int N> __device__ __forceinline__ void cp_wait() {
    asm volatile("cp.async.wait_group %0;" :: "n"(N));
}

// ---------------------------------------------------------------------------
// Prep kernels (run every launch; deterministic; ~15us total)
// ---------------------------------------------------------------------------
__global__ __launch_bounds__(256) void round_x_kernel(const float* __restrict__ x)
{
    int i = blockIdx.x * 256 + threadIdx.x;
    float4 v = *(const float4*)(x + 4 * (size_t)i);
    v.x = to_tf32(v.x); v.y = to_tf32(v.y);
    v.z = to_tf32(v.z); v.w = to_tf32(v.w);
    *(float4*)(g_xr + 4 * (size_t)i) = v;
}

// w_{q,k,v}[h][d][e] -> g_wt[z][h][e][d], rounded. grid (32, 2, 48), block (32, 8)
__global__ __launch_bounds__(256) void transpose_w_kernel(
    const float* __restrict__ wq, const float* __restrict__ wk,
    const float* __restrict__ wv)
{
    __shared__ float t[32][33];
    int zz = blockIdx.z >> 4, h = blockIdx.z & 15;
    const float* src = (zz == 0 ? wq : zz == 1 ? wk : wv) + (size_t)h * DM * DQ;
    int d0 = blockIdx.x * 32, e0 = blockIdx.y * 32;
    int tx = threadIdx.x, ty = threadIdx.y;
#pragma unroll
    for (int r = 0; r < 4; r++)
        t[ty + 8 * r][tx] = to_tf32(src[(size_t)(d0 + ty + 8 * r) * DQ + e0 + tx]);
    __syncthreads();
    float* dst = g_wt + (size_t)blockIdx.z * DQ * DM;
#pragma unroll
    for (int r = 0; r < 4; r++)
        dst[(size_t)(e0 + ty + 8 * r) * DM + d0 + tx] = t[tx][ty + 8 * r];
}

// w_o[k][n] -> g_wot[n][k], rounded. grid (32, 32), block (32, 8)
__global__ __launch_bounds__(256) void transpose_wo_kernel(const float* __restrict__ wo)
{
    __shared__ float t[32][33];
    int k0 = blockIdx.x * 32, n0 = blockIdx.y * 32;
    int tx = threadIdx.x, ty = threadIdx.y;
#pragma unroll
    for (int r = 0; r < 4; r++)
        t[ty + 8 * r][tx] = to_tf32(wo[(size_t)(k0 + ty + 8 * r) * DM + n0 + tx]);
    __syncthreads();
#pragma unroll
    for (int r = 0; r < 4; r++)
        g_wot[(size_t)(n0 + ty + 8 * r) * DM + k0 + tx] = t[tx][ty + 8 * r];
}

// mask any-reduction per (b, 128-row block, 64-col tile). grid 1024, block 256
__global__ __launch_bounds__(256) void mask_reduce_kernel(const uint8_t* __restrict__ mask)
{
    int idx = blockIdx.x;
    int b = idx >> 9, qb = (idx >> 5) & 15, kt = idx & 31;
    int t = threadIdx.x;
    const uint8_t* p = mask + (size_t)b * L_ * L_ +
                       (size_t)(qb * 128 + (t >> 1)) * L_ + kt * 64 + (t & 1) * 32;
    uint4 a = *(const uint4*)p;
    uint4 c = *(const uint4*)(p + 16);
    unsigned any = a.x | a.y | a.z | a.w | c.x | c.y | c.z | c.w;
    int flag = __syncthreads_or((int)(any != 0));
    if (t == 0) g_mflag[idx] = (uint8_t)(flag ? 1 : 0);
}

// ---------------------------------------------------------------------------
// Kernel 1: fused QKV projection, tf32 MMA, cp.async double-buffered.
// Per (z,h): M=4096, N=64, K=1024. Block 128x64, BK=32. 8 warps (4m x 2n).
// ---------------------------------------------------------------------------
__global__ __launch_bounds__(256) void qkv_kernel()
{
    extern __shared__ float sm[];
    float* As = sm;                 // 2 x [128][36]
    float* Bs = sm + 2 * 128 * 36;  // 2 x [64][36]

    const int z  = blockIdx.z;
    const int h  = blockIdx.y;
    const int m0 = blockIdx.x * 128;
    const int tid  = threadIdx.x;
    const int lane = tid & 31;
    const int warp = tid >> 5;
    const int r4 = lane >> 2;
    const int gg = lane & 3;
    const int wm = warp & 3;
    const int wn = warp >> 2;

    const float* Bsrc = g_wt + (size_t)(z * NH + h) * DQ * DM;

    float acc[2][4][4];
#pragma unroll
    for (int i = 0; i < 2; i++)
#pragma unroll
        for (int j = 0; j < 4; j++)
#pragma unroll
            for (int t = 0; t < 4; t++) acc[i][j][t] = 0.f;

    auto load_tile = [&](int kt, int buf) {
        float* Ad = As + buf * (128 * 36);
        float* Bd = Bs + buf * (64 * 36);
        int k0 = kt * 32;
#pragma unroll
        for (int i = 0; i < 4; i++) {
            int f = tid + 256 * i;
            int m = f >> 3, kq = (f & 7) << 2;
            cp16(&Ad[m * 36 + kq], g_xr + (size_t)(m0 + m) * DM + k0 + kq);
        }
#pragma unroll
        for (int i = 0; i < 2; i++) {
            int f = tid + 256 * i;
            int e = f >> 3, kq = (f & 7) << 2;
            cp16(&Bd[e * 36 + kq], Bsrc + (size_t)e * DM + k0 + kq);
        }
    };

    load_tile(0, 0);
    cp_commit();

    for (int kt = 0; kt < 32; kt++) {
        if (kt < 31) { load_tile(kt + 1, (kt + 1) & 1); cp_commit(); cp_wait<1>(); }
        else cp_wait<0>();
        __syncthreads();

        const uint32_t* Au = (const uint32_t*)(As + (kt & 1) * (128 * 36));
        const uint32_t* Bu = (const uint32_t*)(Bs + (kt & 1) * (64 * 36));
#pragma unroll
        for (int ks = 0; ks < 4; ks++) {
            uint32_t a[2][4], b[4][2];
#pragma unroll
            for (int i = 0; i < 2; i++) {
                int row = 32 * wm + 16 * i + r4;
                int cb  = 8 * ks + gg;
                a[i][0] = Au[row * 36 + cb];
                a[i][1] = Au[(row + 8) * 36 + cb];
                a[i][2] = Au[row * 36 + cb + 4];
                a[i][3] = Au[(row + 8) * 36 + cb + 4];
            }
#pragma unroll
            for (int j = 0; j < 4; j++) {
                int col = 32 * wn + 8 * j + r4;
                b[j][0] = Bu[col * 36 + 8 * ks + gg];
                b[j][1] = Bu[col * 36 + 8 * ks + gg + 4];
            }
#pragma unroll
            for (int i = 0; i < 2; i++)
#pragma unroll
                for (int j = 0; j < 4; j++) mma8(acc[i][j], a[i], b[j]);
        }
        __syncthreads();
    }

    if (z < 2) {
        float* O = (z == 0) ? g_q : g_k;
        float s = (z == 0) ? 0.125f : 1.f;   // fold 1/sqrt(dqkv) into Q
#pragma unroll
        for (int i = 0; i < 2; i++) {
            int row = m0 + 32 * wm + 16 * i + r4;
            int b_  = row >> 11;
            int l   = row & (L_ - 1);
            float* base = O + ((((size_t)b_ * NH + h) * L_ + l) << 6);
#pragma unroll
            for (int j = 0; j < 4; j++) {
                int col = 32 * wn + 8 * j + 2 * gg;
                *(float2*)(base + col) =
                    make_float2(to_tf32(acc[i][j][0] * s), to_tf32(acc[i][j][1] * s));
                *(float2*)(base + (8 << 6) + col) =
                    make_float2(to_tf32(acc[i][j][2] * s), to_tf32(acc[i][j][3] * s));
            }
        }
    } else {
        // V: store transposed [b][h][e][l]
#pragma unroll
        for (int i = 0; i < 2; i++) {
            int row = m0 + 32 * wm + 16 * i + r4;
            int b_  = row >> 11;
            int l   = row & (L_ - 1);
            size_t basebh = (size_t)(b_ * NH + h) * DQ;
#pragma unroll
            for (int j = 0; j < 4; j++) {
                int e0 = 32 * wn + 8 * j + 2 * gg;
                g_vt[((basebh + e0)     << 11) + l]     = to_tf32(acc[i][j][0]);
                g_vt[((basebh + e0 + 1) << 11) + l]     = to_tf32(acc[i][j][1]);
                g_vt[((basebh + e0)     << 11) + l + 8] = to_tf32(acc[i][j][2]);
                g_vt[((basebh + e0 + 1) << 11) + l + 8] = to_tf32(acc[i][j][3]);
            }
        }
    }
}

// ---------------------------------------------------------------------------
// Kernel 2: flash attention, tf32 MMA, cp.async double-buffered K/V,
// P kept in registers via shuffle fragment-permutation (no smem round trip).
// smem: Qs[128][68] | Ks[2][64][68] | Vs[2][64][68] = 104448 B -> 2 CTAs/SM
// ---------------------------------------------------------------------------
__global__ __launch_bounds__(256) void attn_kernel(const uint8_t* __restrict__ mask)
{
    extern __shared__ float sm[];
    float* Qs = sm;                    // [128][68]
    float* Ks = Qs + 128 * 68;         // 2 x [64][68]
    float* Vs = Ks + 2 * 64 * 68;      // 2 x [64][68] ([e][l] layout)

    const int tid  = threadIdx.x;
    const int lane = tid & 31;
    const int warp = tid >> 5;
    const int r4 = lane >> 2;
    const int gg = lane & 3;
    const int h  = blockIdx.y;
    const int bb = blockIdx.z;
    const int m0 = blockIdx.x * 128;
    const size_t bh = (size_t)bb * NH + h;

    const float* Qg = g_q + ((bh * L_ + m0) << 6);
    const float* Kg = g_k + (bh << 17);
    const float* Vg = g_vt + (bh << 17);
    const uint8_t* Mg = mask + ((size_t)bb * L_ + m0) * L_;

    // preload per-tile mask flags (32 bytes)
    const uint8_t* fl = g_mflag + (bb * 16 + blockIdx.x) * 32;
    uint4 f0 = *(const uint4*)fl;
    uint4 f1 = *(const uint4*)(fl + 16);
    unsigned fw[8] = {f0.x, f0.y, f0.z, f0.w, f1.x, f1.y, f1.z, f1.w};

    auto load_tile = [&](int t, int buf) {
        float* Kd = Ks + buf * (64 * 68);
        float* Vd = Vs + buf * (64 * 68);
#pragma unroll
        for (int i = 0; i < 4; i++) {
            int f = tid + 256 * i;
            int row = f >> 4, cq = (f & 15) << 2;
            cp16(&Kd[row * 68 + cq], Kg + ((size_t)((t << 6) + row) << 6) + cq);
        }
#pragma unroll
        for (int i = 0; i < 4; i++) {
            int f = tid + 256 * i;
            int e = f >> 4, cq = (f & 15) << 2;
            cp16(&Vd[e * 68 + cq], Vg + ((size_t)e << 11) + (t << 6) + cq);
        }
    };

    // stage Q (already tf32-rounded & pre-scaled) + tile 0, one commit group
#pragma unroll
    for (int i = 0; i < 8; i++) {
        int f = tid + 256 * i;
        int row = f >> 4, cq = (f & 15) << 2;
        cp16(&Qs[row * 68 + cq], Qg + ((size_t)row << 6) + cq);
    }
    load_tile(0, 0);
    cp_commit();

    const int wq = warp * 16;
    float cO[8][4];
#pragma unroll
    for (int j = 0; j < 8; j++)
#pragma unroll
        for (int t = 0; t < 4; t++) cO[j][t] = 0.f;
    float mrow[2] = {-1e30f, -1e30f};
    float lrow[2] = {0.f, 0.f};

    for (int t = 0; t < 32; t++) {
        if (t < 31) { load_tile(t + 1, (t + 1) & 1); cp_commit(); cp_wait<1>(); }
        else cp_wait<0>();
        __syncthreads();

        const uint32_t* Qu = (const uint32_t*)Qs;
        const uint32_t* Ku = (const uint32_t*)(Ks + (t & 1) * (64 * 68));
        const uint32_t* Vu = (const uint32_t*)(Vs + (t & 1) * (64 * 68));

        // S = Q K^T (Q pre-scaled by 0.125)
        float cS[8][4];
#pragma unroll
        for (int j = 0; j < 8; j++)
#pragma unroll
            for (int tt = 0; tt < 4; tt++) cS[j][tt] = 0.f;

#pragma unroll
        for (int ks = 0; ks < 8; ks++) {
            uint32_t a[4];
            int cb = 8 * ks + gg;
            a[0] = Qu[(wq + r4) * 68 + cb];
            a[1] = Qu[(wq + r4 + 8) * 68 + cb];
            a[2] = Qu[(wq + r4) * 68 + cb + 4];
            a[3] = Qu[(wq + r4 + 8) * 68 + cb + 4];
#pragma unroll
            for (int j = 0; j < 8; j++) {
                uint32_t b[2];
                b[0] = Ku[(8 * j + r4) * 68 + cb];
                b[1] = Ku[(8 * j + r4) * 68 + cb + 4];
                mma8(cS[j], a, b);
            }
        }

        // mask (rare path; flag precomputed per CTA-tile)
        if ((fw[t >> 2] >> ((t & 3) * 8)) & 0xff) {
#pragma unroll
            for (int j = 0; j < 8; j++) {
                int col = (t << 6) + 8 * j + 2 * gg;
                const uint8_t* mlo = Mg + (size_t)(wq + r4) * L_ + col;
                const uint8_t* mhi = Mg + (size_t)(wq + r4 + 8) * L_ + col;
                if (mlo[0]) cS[j][0] = -1e9f;
                if (mlo[1]) cS[j][1] = -1e9f;
                if (mhi[0]) cS[j][2] = -1e9f;
                if (mhi[1]) cS[j][3] = -1e9f;
            }
        }

        // online softmax per row-half; write tf32-rounded P into cS
#pragma unroll
        for (int hh = 0; hh < 2; hh++) {
            float mx = -1e30f;
#pragma unroll
            for (int j = 0; j < 8; j++)
                mx = fmaxf(mx, fmaxf(cS[j][2 * hh], cS[j][2 * hh + 1]));
            mx = fmaxf(mx, __shfl_xor_sync(0xffffffffu, mx, 1));
            mx = fmaxf(mx, __shfl_xor_sync(0xffffffffu, mx, 2));
            float newm = fmaxf(mrow[hh], mx);
            float corr = __expf(mrow[hh] - newm);
            mrow[hh] = newm;
            float sum = 0.f;
#pragma unroll
            for (int j = 0; j < 8; j++) {
                float p0 = to_tf32(__expf(cS[j][2 * hh] - newm));
                float p1 = to_tf32(__expf(cS[j][2 * hh + 1] - newm));
                cS[j][2 * hh] = p0;
                cS[j][2 * hh + 1] = p1;
                sum += p0 + p1;
            }
            sum += __shfl_xor_sync(0xffffffffu, sum, 1);
            sum += __shfl_xor_sync(0xffffffffu, sum, 2);
            lrow[hh] = lrow[hh] * corr + sum;
#pragma unroll
            for (int j = 0; j < 8; j++) {
                cO[j][2 * hh] *= corr;
                cO[j][2 * hh + 1] *= corr;
            }
        }

        // O += P V : convert C-fragment (cols 2gg,2gg+1) -> A-fragment (cols gg,gg+4)
        // via intra-quad shuffles, then MMA against V^T tile in smem.
        const int src0 = (lane & ~3) | (gg >> 1);
        const int src1 = src0 | 2;
        const bool odd = (gg & 1);
#pragma unroll
        for (int ks = 0; ks < 8; ks++) {
            float x00 = __shfl_sync(0xffffffffu, cS[ks][0], src0);
            float x01 = __shfl_sync(0xffffffffu, cS[ks][1], src0);
            float x40 = __shfl_sync(0xffffffffu, cS[ks][0], src1);
            float x41 = __shfl_sync(0xffffffffu, cS[ks][1], src1);
            float y00 = __shfl_sync(0xffffffffu, cS[ks][2], src0);
            float y01 = __shfl_sync(0xffffffffu, cS[ks][3], src0);
            float y40 = __shfl_sync(0xffffffffu, cS[ks][2], src1);
            float y41 = __shfl_sync(0xffffffffu, cS[ks][3], src1);
            uint32_t a[4];
            a[0] = __float_as_uint(odd ? x01 : x00);
            a[1] = __float_as_uint(odd ? y01 : y00);
            a[2] = __float_as_uint(odd ? x41 : x40);
            a[3] = __float_as_uint(odd ? y41 : y40);
#pragma unroll
            for (int j = 0; j < 8; j++) {
                uint32_t b[2];
                b[0] = Vu[(8 * j + r4) * 68 + 8 * ks + gg];
                b[1] = Vu[(8 * j + r4) * 68 + 8 * ks + gg + 4];
                mma8(cO[j], a, b);
            }
        }
        __syncthreads();
    }

    // epilogue (tf32-rounded, feeds oproj A operand)
    float inv0 = 1.f / lrow[0];
    float inv1 = 1.f / lrow[1];
    float* Ob = g_o + ((bh * L_ + m0 + wq) << 6);
#pragma unroll
    for (int j = 0; j < 8; j++) {
        int col = 8 * j + 2 * gg;
        *(float2*)(Ob + ((size_t)r4 << 6) + col) =
            make_float2(to_tf32(cO[j][0] * inv0), to_tf32(cO[j][1] * inv0));
        *(float2*)(Ob + ((size_t)(r4 + 8) << 6) + col) =
            make_float2(to_tf32(cO[j][2] * inv1), to_tf32(cO[j][3] * inv1));
    }
}

// ---------------------------------------------------------------------------
// Kernel 3: output projection + residual, tf32 MMA, cp.async double-buffered.
// ---------------------------------------------------------------------------
__global__ __launch_bounds__(256) void oproj_kernel(const float* __restrict__ X)
{
    extern __shared__ float sm[];
    float* As = sm;
    float* Bs = sm + 2 * 128 * 36;

    const int m0 = blockIdx.x * 128;
    const int n0 = blockIdx.y * 64;
    const int tid  = threadIdx.x;
    const int lane = tid & 31;
    const int warp = tid >> 5;
    const int r4 = lane >> 2;
    const int gg = lane & 3;
    const int wm = warp & 3;
    const int wn = warp >> 2;

    float acc[2][4][4];
#pragma unroll
    for (int i = 0; i < 2; i++)
#pragma unroll
        for (int j = 0; j < 4; j++)
#pragma unroll
            for (int t = 0; t < 4; t++) acc[i][j][t] = 0.f;

    auto load_tile = [&](int kt, int buf) {
        float* Ad = As + buf * (128 * 36);
        float* Bd = Bs + buf * (64 * 36);
        int k0 = kt * 32;
        int head = k0 >> 6;
        int ebase = k0 & 63;
#pragma unroll
        for (int i = 0; i < 4; i++) {
            int f = tid + 256 * i;
            int m = f >> 3, kq = (f & 7) << 2;
            int row = m0 + m;
            int b_ = row >> 11, l = row & (L_ - 1);
            cp16(&Ad[m * 36 + kq],
                 g_o + ((((size_t)b_ * NH + head) * L_ + l) << 6) + ebase + kq);
        }
#pragma unroll
        for (int i = 0; i < 2; i++) {
            int f = tid + 256 * i;
            int n = f >> 3, kq = (f & 7) << 2;
            cp16(&Bd[n * 36 + kq], g_wot + (size_t)(n0 + n) * DM + k0 + kq);
        }
    };

    load_tile(0, 0);
    cp_commit();

    for (int kt = 0; kt < 32; kt++) {
        if (kt < 31) { load_tile(kt + 1, (kt + 1) & 1); cp_commit(); cp_wait<1>(); }
        else cp_wait<0>();
        __syncthreads();

        const uint32_t* Au = (const uint32_t*)(As + (kt & 1) * (128 * 36));
        const uint32_t* Bu = (const uint32_t*)(Bs + (kt & 1) * (64 * 36));
#pragma unroll
        for (int ks = 0; ks < 4; ks++) {
            uint32_t a[2][4], b[4][2];
#pragma unroll
            for (int i = 0; i < 2; i++) {
                int row = 32 * wm + 16 * i + r4;
                int cb  = 8 * ks + gg;
                a[i][0] = Au[row * 36 + cb];
                a[i][1] = Au[(row + 8) * 36 + cb];
                a[i][2] = Au[row * 36 + cb + 4];
                a[i][3] = Au[(row + 8) * 36 + cb + 4];
            }
#pragma unroll
            for (int j = 0; j < 4; j++) {
                int col = 32 * wn + 8 * j + r4;
                b[j][0] = Bu[col * 36 + 8 * ks + gg];
                b[j][1] = Bu[col * 36 + 8 * ks + gg + 4];
            }
#pragma unroll
            for (int i = 0; i < 2; i++)
#pragma unroll
                for (int j = 0; j < 4; j++) mma8(acc[i][j], a[i], b[j]);
        }
        __syncthreads();
    }

#pragma unroll
    for (int i = 0; i < 2; i++) {
        int row = m0 + 32 * wm + 16 * i + r4;
#pragma unroll
        for (int j = 0; j < 4; j++) {
            int col = n0 + 32 * wn + 8 * j + 2 * gg;
            float2 x0 = *(const float2*)(X + (size_t)row * DM + col);
            float2 x1 = *(const float2*)(X + (size_t)(row + 8) * DM + col);
            *(float2*)(g_y + (size_t)row * DM + col) =
                make_float2(acc[i][j][0] + x0.x, acc[i][j][1] + x0.y);
            *(float2*)(g_y + (size_t)(row + 8) * DM + col) =
                make_float2(acc[i][j][2] + x1.x, acc[i][j][3] + x1.y);
        }
    }
}

// ---------------------------------------------------------------------------
// Kernel 4: LayerNorm, one block (256 threads) per row of 1024.
// ---------------------------------------------------------------------------
__global__ __launch_bounds__(256) void ln_kernel(
    const float* __restrict__ gamma, const float* __restrict__ beta,
    float* __restrict__ out)
{
    const int row = blockIdx.x;
    const int tid = threadIdx.x;
    const float* Y = g_y + (size_t)row * DM;

    float4 v = *(const float4*)(Y + (tid << 2));
    float s  = v.x + v.y + v.z + v.w;
    float sq = v.x * v.x + v.y * v.y + v.z * v.z + v.w * v.w;

#pragma unroll
    for (int off = 16; off > 0; off >>= 1) {
        s  += __shfl_xor_sync(0xffffffffu, s, off);
        sq += __shfl_xor_sync(0xffffffffu, sq, off);
    }

    __shared__ float red[18];
    const int wid = tid >> 5;
    if ((tid & 31) == 0) { red[wid] = s; red[wid + 8] = sq; }
    __syncthreads();
    if (tid == 0) {
        float ts = 0.f, tq = 0.f;
#pragma unroll
        for (int w = 0; w < 8; w++) { ts += red[w]; tq += red[w + 8]; }
        float mu  = ts * (1.f / DM);
        float var = tq * (1.f / DM) - mu * mu;
        red[16] = mu;
        red[17] = rsqrtf(var + 1e-5f);
    }
    __syncthreads();
    float mu   = red[16];
    float rstd = red[17];

    float4 g = *(const float4*)(gamma + (tid << 2));
    float4 b = *(const float4*)(beta  + (tid << 2));
    float4 res;
    res.x = (v.x - mu) * rstd * g.x + b.x;
    res.y = (v.y - mu) * rstd * g.y + b.y;
    res.z = (v.z - mu) * rstd * g.z + b.z;
    res.w = (v.w - mu) * rstd * g.w + b.w;
    *(float4*)(out + (size_t)row * DM + (tid << 2)) = res;
}

// ---------------------------------------------------------------------------
// Launch
// ---------------------------------------------------------------------------
extern "C" void kernel_launch(void* const* d_in, const int* in_sizes, int n_in,
                              void* d_out, int out_size)
{
    const float*   x     = (const float*)d_in[0];
    const uint8_t* mask  = (const uint8_t*)d_in[1];
    const float*   wq    = (const float*)d_in[2];
    const float*   wk    = (const float*)d_in[3];
    const float*   wv    = (const float*)d_in[4];
    const float*   wo    = (const float*)d_in[5];
    const float*   gamma = (const float*)d_in[6];
    const float*   beta  = (const float*)d_in[7];
    float*         out   = (float*)d_out;

    const int gemm_smem = (2 * 128 * 36 + 2 * 64 * 36) * 4;         // 55296
    const int attn_smem = (128 * 68 + 2 * 64 * 68 + 2 * 64 * 68) * 4; // 104448
    cudaFuncSetAttribute(qkv_kernel,
                         cudaFuncAttributeMaxDynamicSharedMemorySize, gemm_smem);
    cudaFuncSetAttribute(attn_kernel,
                         cudaFuncAttributeMaxDynamicSharedMemorySize, attn_smem);
    cudaFuncSetAttribute(oproj_kernel,
                         cudaFuncAttributeMaxDynamicSharedMemorySize, gemm_smem);

    // prep (independent)
    round_x_kernel<<<(B_ * L_ * DM) / 1024, 256>>>(x);
    transpose_w_kernel<<<dim3(32, 2, 48), dim3(32, 8)>>>(wq, wk, wv);
    transpose_wo_kernel<<<dim3(32, 32), dim3(32, 8)>>>(wo);
    mask_reduce_kernel<<<B_ * 16 * 32, 256>>>(mask);

    dim3 g1((B_ * L_) / 128, NH, 3);
    qkv_kernel<<<g1, 256, gemm_smem>>>();

    dim3 g2(L_ / 128, NH, B_);
    attn_kernel<<<g2, 256, attn_smem>>>(mask);

    dim3 g3((B_ * L_) / 128, DM / 64);
    oproj_kernel<<<g3, 256, gemm_smem>>>(x);

    ln_kernel<<<B_ * L_, 256>>>(gamma, beta, out);
}

// round 10
// speedup vs baseline: 1.3768x; 1.3768x over previous
#include <cuda_runtime.h>
#include <cstdint>

#define B_  2
#define L_  2048
#define DM  1024
#define NH  16
#define DQ  64

// Scratch (allocation-free rule: __device__ globals)
__device__ float g_q[(size_t)B_ * NH * L_ * DQ];   // pre-scaled by 0.125
__device__ float g_k[(size_t)B_ * NH * L_ * DQ];
__device__ float g_v[(size_t)B_ * NH * L_ * DQ];
__device__ float g_o[(size_t)B_ * NH * L_ * DQ];
__device__ float g_y[(size_t)B_ * L_ * DM];
__device__ __align__(16) uint8_t g_mflag[B_ * 16 * 32]; // per (b, qblock128, ktile64)

__device__ __forceinline__ float to_tf32(float x) {
    asm("cvt.rna.tf32.f32 %0, %0;" : "+f"(x));
    return x;
}

__device__ __forceinline__ void mma8(float c[4], const uint32_t a[4], const uint32_t b[2]) {
    asm volatile(
        "mma.sync.aligned.m16n8k8.row.col.f32.tf32.tf32.f32 "
        "{%0,%1,%2,%3},{%4,%5,%6,%7},{%8,%9},{%0,%1,%2,%3};"
        : "+f"(c[0]), "+f"(c[1]), "+f"(c[2]), "+f"(c[3])
        : "r"(a[0]), "r"(a[1]), "r"(a[2]), "r"(a[3]), "r"(b[0]), "r"(b[1]));
}

// ---------------------------------------------------------------------------
// Prep: mask any-reduction per (b, 128-row block, 64-col tile). grid 1024
// ---------------------------------------------------------------------------
__global__ __launch_bounds__(256) void mask_reduce_kernel(const uint8_t* __restrict__ mask)
{
    int idx = blockIdx.x;
    int b = idx >> 9, qb = (idx >> 5) & 15, kt = idx & 31;
    int t = threadIdx.x;
    const uint8_t* p = mask + (size_t)b * L_ * L_ +
                       (size_t)(qb * 128 + (t >> 1)) * L_ + kt * 64 + (t & 1) * 32;
    uint4 a = *(const uint4*)p;
    uint4 c = *(const uint4*)(p + 16);
    unsigned any = a.x | a.y | a.z | a.w | c.x | c.y | c.z | c.w;
    int flag = __syncthreads_or((int)(any != 0));
    if (t == 0) g_mflag[idx] = (uint8_t)(flag ? 1 : 0);
}

// ---------------------------------------------------------------------------
// Kernel 1: fused QKV projection with tf32 MMA (round-4 proven body).
// Per (z, h): GEMM M=4096, N=64, K=1024. Block tile 128x64, BK=32.
// 8 warps in 4(m) x 2(n); warp tile 32x32. Q epilogue folds 0.125.
// ---------------------------------------------------------------------------
__global__ __launch_bounds__(256) void qkv_kernel(
    const float* __restrict__ X,
    const float* __restrict__ Wq,
    const float* __restrict__ Wk,
    const float* __restrict__ Wv)
{
    __shared__ float As[128 * 36];
    __shared__ float Bs[64 * 36];

    const float* W;
    float* O;
    if (blockIdx.z == 0)      { W = Wq; O = g_q; }
    else if (blockIdx.z == 1) { W = Wk; O = g_k; }
    else                      { W = Wv; O = g_v; }

    const int h  = blockIdx.y;
    const int m0 = blockIdx.x * 128;
    const int tid  = threadIdx.x;
    const int lane = tid & 31;
    const int warp = tid >> 5;
    const int r4 = lane >> 2;
    const int gg = lane & 3;
    const int wm = warp & 3;
    const int wn = warp >> 2;

    const float* Wh = W + (size_t)h * DM * DQ;

    float acc[2][4][4];
#pragma unroll
    for (int i = 0; i < 2; i++)
#pragma unroll
        for (int j = 0; j < 4; j++)
#pragma unroll
            for (int t = 0; t < 4; t++) acc[i][j][t] = 0.f;

    const int eB  = tid & 63;
    const int kq0 = tid >> 6;

    for (int k0 = 0; k0 < DM; k0 += 32) {
#pragma unroll
        for (int i = 0; i < 4; i++) {
            int f = tid + 256 * i;
            int m = f >> 3, kq = f & 7;
            float4 v = *(const float4*)(X + (size_t)(m0 + m) * DM + k0 + 4 * kq);
            v.x = to_tf32(v.x); v.y = to_tf32(v.y);
            v.z = to_tf32(v.z); v.w = to_tf32(v.w);
            *(float4*)&As[m * 36 + 4 * kq] = v;
        }
#pragma unroll
        for (int p = 0; p < 2; p++) {
            int kq = kq0 + 4 * p;
            const float* src = Wh + (size_t)(k0 + 4 * kq) * DQ + eB;
            float4 v;
            v.x = to_tf32(src[0]);
            v.y = to_tf32(src[DQ]);
            v.z = to_tf32(src[2 * DQ]);
            v.w = to_tf32(src[3 * DQ]);
            *(float4*)&Bs[eB * 36 + 4 * kq] = v;
        }
        __syncthreads();

        const uint32_t* Au = (const uint32_t*)As;
        const uint32_t* Bu = (const uint32_t*)Bs;
#pragma unroll
        for (int ks = 0; ks < 4; ks++) {
            uint32_t a[2][4], b[4][2];
#pragma unroll
            for (int i = 0; i < 2; i++) {
                int row = 32 * wm + 16 * i + r4;
                int cb  = 8 * ks + gg;
                a[i][0] = Au[row * 36 + cb];
                a[i][1] = Au[(row + 8) * 36 + cb];
                a[i][2] = Au[row * 36 + cb + 4];
                a[i][3] = Au[(row + 8) * 36 + cb + 4];
            }
#pragma unroll
            for (int j = 0; j < 4; j++) {
                int col = 32 * wn + 8 * j + r4;
                b[j][0] = Bu[col * 36 + 8 * ks + gg];
                b[j][1] = Bu[col * 36 + 8 * ks + gg + 4];
            }
#pragma unroll
            for (int i = 0; i < 2; i++)
#pragma unroll
                for (int j = 0; j < 4; j++) mma8(acc[i][j], a[i], b[j]);
        }
        __syncthreads();
    }

    const float s = (blockIdx.z == 0) ? 0.125f : 1.f;  // fold 1/sqrt(dqkv) into Q
#pragma unroll
    for (int i = 0; i < 2; i++) {
        int row = m0 + 32 * wm + 16 * i + r4;
        int b_  = row >> 11;
        int l   = row & (L_ - 1);
        float* base = O + ((((size_t)b_ * NH + h) * L_ + l) << 6);
#pragma unroll
        for (int j = 0; j < 4; j++) {
            int col = 32 * wn + 8 * j + 2 * gg;
            *(float2*)(base + col) = make_float2(acc[i][j][0] * s, acc[i][j][1] * s);
            *(float2*)(base + (8 << 6) + col) = make_float2(acc[i][j][2] * s, acc[i][j][3] * s);
        }
    }
}

// ---------------------------------------------------------------------------
// Kernel 2: flash attention, tf32 MMA.
// CTA = 128 query rows, 4 warps x 32 rows (halves B-fragment crossbar bytes
// vs 8x16). Key tiles of 64. P through smem. Mask via precomputed flags.
// Dynamic smem: Qs[128][68] | Ks[64][68] | Vs[64][68] | Ps[128][68] = 104448
// ---------------------------------------------------------------------------
__global__ __launch_bounds__(128) void attn_kernel(const uint8_t* __restrict__ mask)
{
    extern __shared__ float sm[];
    float* Qs = sm;                    // [128][68]
    float* Ks = Qs + 128 * 68;         // [64][68]
    float* Vs = Ks + 64 * 68;          // [64][68] ([e][l] layout)
    float* Ps = Vs + 64 * 68;          // [128][68]

    const int tid  = threadIdx.x;
    const int lane = tid & 31;
    const int warp = tid >> 5;
    const int r4 = lane >> 2;
    const int gg = lane & 3;
    const int h  = blockIdx.y;
    const int bb = blockIdx.z;
    const int m0 = blockIdx.x * 128;
    const size_t bh = (size_t)bb * NH + h;

    const float* Qg = g_q + ((bh * L_ + m0) << 6);
    const float* Kg = g_k + ((bh * L_) << 6);
    const float* Vg = g_v + ((bh * L_) << 6);
    const uint8_t* Mg = mask + ((size_t)bb * L_ + m0) * L_;

    // per-tile mask flags (32 bytes)
    const uint8_t* fl = g_mflag + (bb * 16 + blockIdx.x) * 32;
    uint4 f0 = *(const uint4*)fl;
    uint4 f1 = *(const uint4*)(fl + 16);
    unsigned fw[8] = {f0.x, f0.y, f0.z, f0.w, f1.x, f1.y, f1.z, f1.w};

    // Stage Q (tf32; already pre-scaled by 0.125)
#pragma unroll
    for (int i = 0; i < 16; i++) {
        int f = tid + 128 * i;
        int row = f >> 4, eq = f & 15;
        float4 v = *(const float4*)(Qg + ((size_t)row << 6) + 4 * eq);
        v.x = to_tf32(v.x); v.y = to_tf32(v.y);
        v.z = to_tf32(v.z); v.w = to_tf32(v.w);
        *(float4*)&Qs[row * 68 + 4 * eq] = v;
    }

    const int wq = warp * 32;          // 32 rows per warp
    float cO[2][8][4];
#pragma unroll
    for (int i = 0; i < 2; i++)
#pragma unroll
        for (int j = 0; j < 8; j++)
#pragma unroll
            for (int t = 0; t < 4; t++) cO[i][j][t] = 0.f;
    float mrow[2][2] = {{-1e30f, -1e30f}, {-1e30f, -1e30f}};
    float lrow[2][2] = {{0.f, 0.f}, {0.f, 0.f}};

    const int eV  = tid & 63;
    const int kqV = tid >> 6;          // 0..1

    for (int kb = 0; kb < L_; kb += 64) {
        __syncthreads();
        // K tile (64 x 64)
#pragma unroll
        for (int i = 0; i < 8; i++) {
            int f = tid + 128 * i;
            int row = f >> 4, eq = f & 15;
            float4 v = *(const float4*)(Kg + ((size_t)(kb + row) << 6) + 4 * eq);
            v.x = to_tf32(v.x); v.y = to_tf32(v.y);
            v.z = to_tf32(v.z); v.w = to_tf32(v.w);
            *(float4*)&Ks[row * 68 + 4 * eq] = v;
        }
        // V^T tile ([e][l])
#pragma unroll
        for (int p = 0; p < 8; p++) {
            int kq = kqV + 2 * p;
            const float* src = Vg + ((size_t)(kb + 4 * kq) << 6) + eV;
            float4 v;
            v.x = to_tf32(src[0]);
            v.y = to_tf32(src[64]);
            v.z = to_tf32(src[128]);
            v.w = to_tf32(src[192]);
            *(float4*)&Vs[eV * 68 + 4 * kq] = v;
        }
        __syncthreads();

        const int t = kb >> 6;
        const uint32_t* Qu = (const uint32_t*)Qs;
        const uint32_t* Ku = (const uint32_t*)Ks;
        const uint32_t* Vu = (const uint32_t*)Vs;

        // S = Q K^T  (two m16 fragments per warp)
        float cS[2][8][4];
#pragma unroll
        for (int i = 0; i < 2; i++)
#pragma unroll
            for (int j = 0; j < 8; j++)
#pragma unroll
                for (int tt = 0; tt < 4; tt++) cS[i][j][tt] = 0.f;

#pragma unroll
        for (int ks = 0; ks < 8; ks++) {
            int cb = 8 * ks + gg;
            uint32_t a[2][4];
#pragma unroll
            for (int i = 0; i < 2; i++) {
                int row = wq + 16 * i + r4;
                a[i][0] = Qu[row * 68 + cb];
                a[i][1] = Qu[(row + 8) * 68 + cb];
                a[i][2] = Qu[row * 68 + cb + 4];
                a[i][3] = Qu[(row + 8) * 68 + cb + 4];
            }
#pragma unroll
            for (int j = 0; j < 8; j++) {
                uint32_t b[2];
                b[0] = Ku[(8 * j + r4) * 68 + cb];
                b[1] = Ku[(8 * j + r4) * 68 + cb + 4];
#pragma unroll
                for (int i = 0; i < 2; i++) mma8(cS[i][j], a[i], b);
            }
        }

        // mask (rare path; flag precomputed)
        if ((fw[t >> 2] >> ((t & 3) * 8)) & 0xff) {
#pragma unroll
            for (int i = 0; i < 2; i++)
#pragma unroll
                for (int j = 0; j < 8; j++) {
                    int col = kb + 8 * j + 2 * gg;
                    const uint8_t* mlo = Mg + (size_t)(wq + 16 * i + r4) * L_ + col;
                    const uint8_t* mhi = Mg + (size_t)(wq + 16 * i + r4 + 8) * L_ + col;
                    if (mlo[0]) cS[i][j][0] = -1e9f;
                    if (mlo[1]) cS[i][j][1] = -1e9f;
                    if (mhi[0]) cS[i][j][2] = -1e9f;
                    if (mhi[1]) cS[i][j][3] = -1e9f;
                }
        }

        // online softmax per (fragment, row-half)
#pragma unroll
        for (int i = 0; i < 2; i++)
#pragma unroll
            for (int hh = 0; hh < 2; hh++) {
                float mx = -1e30f;
#pragma unroll
                for (int j = 0; j < 8; j++)
                    mx = fmaxf(mx, fmaxf(cS[i][j][2 * hh], cS[i][j][2 * hh + 1]));
                mx = fmaxf(mx, __shfl_xor_sync(0xffffffffu, mx, 1));
                mx = fmaxf(mx, __shfl_xor_sync(0xffffffffu, mx, 2));
                float newm = fmaxf(mrow[i][hh], mx);
                float corr = __expf(mrow[i][hh] - newm);
                mrow[i][hh] = newm;
                float sum = 0.f;
#pragma unroll
                for (int j = 0; j < 8; j++) {
                    float p0 = __expf(cS[i][j][2 * hh] - newm);
                    float p1 = __expf(cS[i][j][2 * hh + 1] - newm);
                    cS[i][j][2 * hh] = p0;
                    cS[i][j][2 * hh + 1] = p1;
                    sum += p0 + p1;
                }
                sum += __shfl_xor_sync(0xffffffffu, sum, 1);
                sum += __shfl_xor_sync(0xffffffffu, sum, 2);
                lrow[i][hh] = lrow[i][hh] * corr + sum;
#pragma unroll
                for (int j = 0; j < 8; j++) {
                    cO[i][j][2 * hh] *= corr;
                    cO[i][j][2 * hh + 1] *= corr;
                }
            }

        // store P (tf32) to this warp's rows of Ps
#pragma unroll
        for (int i = 0; i < 2; i++)
#pragma unroll
            for (int j = 0; j < 8; j++) {
                int row = wq + 16 * i + r4;
                *(float2*)&Ps[row * 68 + 8 * j + 2 * gg] =
                    make_float2(to_tf32(cS[i][j][0]), to_tf32(cS[i][j][1]));
                *(float2*)&Ps[(row + 8) * 68 + 8 * j + 2 * gg] =
                    make_float2(to_tf32(cS[i][j][2]), to_tf32(cS[i][j][3]));
            }
        __syncwarp();

        // O += P V
        const uint32_t* Pu = (const uint32_t*)Ps;
#pragma unroll
        for (int ks = 0; ks < 8; ks++) {
            int cb = 8 * ks + gg;
            uint32_t a[2][4];
#pragma unroll
            for (int i = 0; i < 2; i++) {
                int row = wq + 16 * i + r4;
                a[i][0] = Pu[row * 68 + cb];
                a[i][1] = Pu[(row + 8) * 68 + cb];
                a[i][2] = Pu[row * 68 + cb + 4];
                a[i][3] = Pu[(row + 8) * 68 + cb + 4];
            }
#pragma unroll
            for (int j = 0; j < 8; j++) {
                uint32_t b[2];
                b[0] = Vu[(8 * j + r4) * 68 + cb];
                b[1] = Vu[(8 * j + r4) * 68 + cb + 4];
#pragma unroll
                for (int i = 0; i < 2; i++) mma8(cO[i][j], a[i], b);
            }
        }
    }

    // epilogue
#pragma unroll
    for (int i = 0; i < 2; i++) {
        float inv0 = 1.f / lrow[i][0];
        float inv1 = 1.f / lrow[i][1];
        float* Ob = g_o + ((bh * L_ + m0 + wq + 16 * i) << 6);
#pragma unroll
        for (int j = 0; j < 8; j++) {
            int col = 8 * j + 2 * gg;
            *(float2*)(Ob + ((size_t)r4 << 6) + col) =
                make_float2(cO[i][j][0] * inv0, cO[i][j][1] * inv0);
            *(float2*)(Ob + ((size_t)(r4 + 8) << 6) + col) =
                make_float2(cO[i][j][2] * inv1, cO[i][j][3] * inv1);
        }
    }
}

// ---------------------------------------------------------------------------
// Kernel 3: output projection + residual with tf32 MMA (round-4 proven body).
// GEMM M=4096, N=1024, K=1024. Block tile 128x64, BK=32.
// ---------------------------------------------------------------------------
__global__ __launch_bounds__(256) void oproj_kernel(
    const float* __restrict__ X, const float* __restrict__ Wo)
{
    __shared__ float As[128 * 36];
    __shared__ float Bs[64 * 36];

    const int m0 = blockIdx.x * 128;
    const int n0 = blockIdx.y * 64;
    const int tid  = threadIdx.x;
    const int lane = tid & 31;
    const int warp = tid >> 5;
    const int r4 = lane >> 2;
    const int gg = lane & 3;
    const int wm = warp & 3;
    const int wn = warp >> 2;

    float acc[2][4][4];
#pragma unroll
    for (int i = 0; i < 2; i++)
#pragma unroll
        for (int j = 0; j < 4; j++)
#pragma unroll
            for (int t = 0; t < 4; t++) acc[i][j][t] = 0.f;

    const int eB  = tid & 63;
    const int kq0 = tid >> 6;

    for (int k0 = 0; k0 < DM; k0 += 32) {
#pragma unroll
        for (int i = 0; i < 4; i++) {
            int f = tid + 256 * i;
            int m = f >> 3, kq = f & 7;
            int row = m0 + m;
            int b_ = row >> 11, l = row & (L_ - 1);
            int k  = k0 + 4 * kq;
            int hk = k >> 6, ek = k & 63;
            float4 v = *(const float4*)(
                g_o + ((((size_t)b_ * NH + hk) * L_ + l) << 6) + ek);
            v.x = to_tf32(v.x); v.y = to_tf32(v.y);
            v.z = to_tf32(v.z); v.w = to_tf32(v.w);
            *(float4*)&As[m * 36 + 4 * kq] = v;
        }
#pragma unroll
        for (int p = 0; p < 2; p++) {
            int kq = kq0 + 4 * p;
            const float* src = Wo + (size_t)(k0 + 4 * kq) * DM + n0 + eB;
            float4 v;
            v.x = to_tf32(src[0]);
            v.y = to_tf32(src[DM]);
            v.z = to_tf32(src[2 * DM]);
            v.w = to_tf32(src[3 * DM]);
            *(float4*)&Bs[eB * 36 + 4 * kq] = v;
        }
        __syncthreads();

        const uint32_t* Au = (const uint32_t*)As;
        const uint32_t* Bu = (const uint32_t*)Bs;
#pragma unroll
        for (int ks = 0; ks < 4; ks++) {
            uint32_t a[2][4], b[4][2];
#pragma unroll
            for (int i = 0; i < 2; i++) {
                int row = 32 * wm + 16 * i + r4;
                int cb  = 8 * ks + gg;
                a[i][0] = Au[row * 36 + cb];
                a[i][1] = Au[(row + 8) * 36 + cb];
                a[i][2] = Au[row * 36 + cb + 4];
                a[i][3] = Au[(row + 8) * 36 + cb + 4];
            }
#pragma unroll
            for (int j = 0; j < 4; j++) {
                int col = 32 * wn + 8 * j + r4;
                b[j][0] = Bu[col * 36 + 8 * ks + gg];
                b[j][1] = Bu[col * 36 + 8 * ks + gg + 4];
            }
#pragma unroll
            for (int i = 0; i < 2; i++)
#pragma unroll
                for (int j = 0; j < 4; j++) mma8(acc[i][j], a[i], b[j]);
        }
        __syncthreads();
    }

#pragma unroll
    for (int i = 0; i < 2; i++) {
        int row = m0 + 32 * wm + 16 * i + r4;
#pragma unroll
        for (int j = 0; j < 4; j++) {
            int col = n0 + 32 * wn + 8 * j + 2 * gg;
            float2 x0 = *(const float2*)(X + (size_t)row * DM + col);
            float2 x1 = *(const float2*)(X + (size_t)(row + 8) * DM + col);
            *(float2*)(g_y + (size_t)row * DM + col) =
                make_float2(acc[i][j][0] + x0.x, acc[i][j][1] + x0.y);
            *(float2*)(g_y + (size_t)(row + 8) * DM + col) =
                make_float2(acc[i][j][2] + x1.x, acc[i][j][3] + x1.y);
        }
    }
}

// ---------------------------------------------------------------------------
// Kernel 4: LayerNorm, one block (256 threads) per row of 1024.
// ---------------------------------------------------------------------------
__global__ __launch_bounds__(256) void ln_kernel(
    const float* __restrict__ gamma, const float* __restrict__ beta,
    float* __restrict__ out)
{
    const int row = blockIdx.x;
    const int tid = threadIdx.x;
    const float* Y = g_y + (size_t)row * DM;

    float4 v = *(const float4*)(Y + (tid << 2));
    float s  = v.x + v.y + v.z + v.w;
    float sq = v.x * v.x + v.y * v.y + v.z * v.z + v.w * v.w;

#pragma unroll
    for (int off = 16; off > 0; off >>= 1) {
        s  += __shfl_xor_sync(0xffffffffu, s, off);
        sq += __shfl_xor_sync(0xffffffffu, sq, off);
    }

    __shared__ float red[18];
    const int wid = tid >> 5;
    if ((tid & 31) == 0) { red[wid] = s; red[wid + 8] = sq; }
    __syncthreads();
    if (tid == 0) {
        float ts = 0.f, tq = 0.f;
#pragma unroll
        for (int w = 0; w < 8; w++) { ts += red[w]; tq += red[w + 8]; }
        float mu  = ts * (1.f / DM);
        float var = tq * (1.f / DM) - mu * mu;
        red[16] = mu;
        red[17] = rsqrtf(var + 1e-5f);
    }
    __syncthreads();
    float mu   = red[16];
    float rstd = red[17];

    float4 g = *(const float4*)(gamma + (tid << 2));
    float4 b = *(const float4*)(beta  + (tid << 2));
    float4 res;
    res.x = (v.x - mu) * rstd * g.x + b.x;
    res.y = (v.y - mu) * rstd * g.y + b.y;
    res.z = (v.z - mu) * rstd * g.z + b.z;
    res.w = (v.w - mu) * rstd * g.w + b.w;
    *(float4*)(out + (size_t)row * DM + (tid << 2)) = res;
}

// ---------------------------------------------------------------------------
// Launch
// ---------------------------------------------------------------------------
extern "C" void kernel_launch(void* const* d_in, const int* in_sizes, int n_in,
                              void* d_out, int out_size)
{
    const float*   x     = (const float*)d_in[0];
    const uint8_t* mask  = (const uint8_t*)d_in[1];
    const float*   wq    = (const float*)d_in[2];
    const float*   wk    = (const float*)d_in[3];
    const float*   wv    = (const float*)d_in[4];
    const float*   wo    = (const float*)d_in[5];
    const float*   gamma = (const float*)d_in[6];
    const float*   beta  = (const float*)d_in[7];
    float*         out   = (float*)d_out;

    const int attn_smem = (128 * 68 + 64 * 68 + 64 * 68 + 128 * 68) * 4; // 104448
    cudaFuncSetAttribute(attn_kernel,
                         cudaFuncAttributeMaxDynamicSharedMemorySize, attn_smem);

    mask_reduce_kernel<<<B_ * 16 * 32, 256>>>(mask);

    dim3 g1((B_ * L_) / 128, NH, 3);
    qkv_kernel<<<g1, 256>>>(x, wq, wk, wv);

    dim3 g2(L_ / 128, NH, B_);
    attn_kernel<<<g2, 128, attn_smem>>>(mask);

    dim3 g3((B_ * L_) / 128, DM / 64);
    oproj_kernel<<<g3, 256>>>(x, wo);

    ln_kernel<<<B_ * L_, 256>>>(gamma, beta, out);
}